// round 16
// baseline (speedup 1.0000x reference)
#include <cuda_runtime.h>
#include <cuda_fp16.h>
#include <math.h>
#include <cstdint>

#define N_TOK 16384
#define DMODEL 896
#define KMAX 3584   // [h | alpha*u | ug | h*ug]
#define INV_SQRT_D 0.03340766f

// ---------------- scratch (device globals) ----------------
__device__ float g_logit_part[N_TOK * 8];
__device__ float g_logit[N_TOK];
__device__ __align__(16) __half g_A[(size_t)N_TOK * KMAX];          // f16 activations
__device__ __align__(16) __half g_Wa[DMODEL * DMODEL];
__device__ __align__(16) __half g_Wg[DMODEL * 2 * DMODEL];
__device__ __align__(16) __half g_Wf[DMODEL * 3 * DMODEL];

// ---------------- helpers ----------------
static __device__ __forceinline__ uint32_t smem_u32(const void* p) {
    uint32_t a;
    asm("{ .reg .u64 t; cvta.to.shared.u64 t, %1; cvt.u32.u64 %0, t; }" : "=r"(a) : "l"(p));
    return a;
}
static __device__ __forceinline__ void cp16(uint32_t s, const void* g) {
    asm volatile("cp.async.cg.shared.global [%0], [%1], 16;" :: "r"(s), "l"(g));
}
#define CP_COMMIT() asm volatile("cp.async.commit_group;" ::: "memory")
#define CP_WAIT0()  asm volatile("cp.async.wait_group 0;" ::: "memory")

static __device__ __forceinline__ void ldmx4(uint32_t* r, uint32_t addr) {
    asm volatile("ldmatrix.sync.aligned.m8n8.x4.shared.b16 {%0,%1,%2,%3}, [%4];"
        : "=r"(r[0]), "=r"(r[1]), "=r"(r[2]), "=r"(r[3]) : "r"(addr));
}
static __device__ __forceinline__ void mma16816(float* c, const uint32_t* a,
                                                uint32_t b0, uint32_t b1) {
    asm volatile("mma.sync.aligned.m16n8k16.row.col.f32.f16.f16.f32 "
        "{%0,%1,%2,%3}, {%4,%5,%6,%7}, {%8,%9}, {%0,%1,%2,%3};"
        : "+f"(c[0]), "+f"(c[1]), "+f"(c[2]), "+f"(c[3])
        : "r"(a[0]), "r"(a[1]), "r"(a[2]), "r"(a[3]), "r"(b0), "r"(b1));
}

static __device__ __forceinline__ void f16_store4(__half* dst, size_t idx, float4 v) {
    uint32_t p01, p23;
    asm("cvt.rn.f16x2.f32 %0, %1, %2;" : "=r"(p01) : "f"(v.y), "f"(v.x));
    asm("cvt.rn.f16x2.f32 %0, %1, %2;" : "=r"(p23) : "f"(v.w), "f"(v.z));
    *(uint2*)(dst + idx) = make_uint2(p01, p23);
}
static __device__ __forceinline__ void f16_store2(__half* dst, size_t idx, float2 v) {
    uint32_t p;
    asm("cvt.rn.f16x2.f32 %0, %1, %2;" : "=r"(p) : "f"(v.y), "f"(v.x));
    *(uint32_t*)(dst + idx) = p;
}

// ---------------- fused conversion kernel ----------------
#define NA_ITEMS (N_TOK * 224 * 2)
#define NW_ITEMS (DMODEL * (DMODEL + 2 * DMODEL + 3 * DMODEL) / 4)
__global__ void k_conv_all(const float* __restrict__ h, const float* __restrict__ u,
                           const float* __restrict__ wa, const float* __restrict__ wg,
                           const float* __restrict__ wf) {
    int i = blockIdx.x * blockDim.x + threadIdx.x;
    const int half = N_TOK * 224;
    if (i < half) {
        int row = i / 224, c4 = (i % 224) * 4;
        f16_store4(g_A, (size_t)row * KMAX + c4,
                   *(const float4*)(h + (size_t)row * DMODEL + c4));
    } else if (i < 2 * half) {
        int j = i - half;
        int row = j / 224, c4 = (j % 224) * 4;
        f16_store4(g_A, (size_t)row * KMAX + DMODEL + c4,
                   *(const float4*)(u + (size_t)row * DMODEL + c4));
    } else {
        int j = i - 2 * half;
        const int n1 = DMODEL * DMODEL / 4;
        const int n2 = DMODEL * 2 * DMODEL / 4;
        const int n3 = DMODEL * 3 * DMODEL / 4;
        if (j < n1) {
            f16_store4(g_Wa, (size_t)j * 4, ((const float4*)wa)[j]);
        } else if (j < n1 + n2) {
            int k = j - n1;
            f16_store4(g_Wg, (size_t)k * 4, ((const float4*)wg)[k]);
        } else if (j < n1 + n2 + n3) {
            int k = j - n1 - n2;
            f16_store4(g_Wf, (size_t)k * 4, ((const float4*)wf)[k]);
        }
    }
}

// one warp per row: reduce logit partials, compute alpha, write f16 alpha*u into A[896:1792]
__global__ void k_alpha(const float* __restrict__ u) {
    const int row = blockIdx.x * 8 + (threadIdx.x >> 5);
    const int l = threadIdx.x & 31;
    float s = (l < 7) ? g_logit_part[(size_t)row * 8 + l] : 0.f;
    s += __shfl_xor_sync(0xffffffffu, s, 1);
    s += __shfl_xor_sync(0xffffffffu, s, 2);
    s += __shfl_xor_sync(0xffffffffu, s, 4);
    s = __shfl_sync(0xffffffffu, s, 0);
    if (l == 0) g_logit[row] = s;
    const float a = 1.f / (1.f + __expf(-s * INV_SQRT_D));
    const float* ur = u + (size_t)row * DMODEL;
    const size_t base = (size_t)row * KMAX + DMODEL;
#pragma unroll
    for (int j = 0; j < 7; j++) {
        const int c4 = (j * 32 + l) * 4;
        float4 v = *(const float4*)(ur + c4);
        v.x *= a; v.y *= a; v.z *= a; v.w *= a;
        f16_store4(g_A, base + c4, v);
    }
}

// ---------------- f16 single-pass HMMA GEMM: 64x128 CTA tile, 128 thr, 4 CTAs/SM ----------------
// kc=64, single sync per iteration
#define ROWB    144
#define T_A     0
#define T_B     (64 * ROWB)            // A: 64 rows
#define STAGE_B ((64 + 128) * ROWB)    // 27648
#define SMEM_BYTES (2 * STAGE_B)       // 55296; 4 CTAs = 221184 <= 228KB

// MODE 0: K=896 (A = u slot). Epi: logit partials
// MODE 1: K=1792 (A=[h|alpha u]). Epi: ug -> A[1792:2688], h*ug -> A[2688:3584]
// MODE 2: K=2688 (A = {[0:896),[1792:3584)}). Epi: dst = gelu_erf(z)
template <int MODE>
__global__ void __launch_bounds__(128, 4) hgemm(
    const float* __restrict__ hmat, const float* __restrict__ umat,
    const __half* __restrict__ W, const float* __restrict__ bias,
    float* __restrict__ dst)
{
    constexpr int K = (MODE == 0) ? 896 : (MODE == 1 ? 1792 : 2688);
    constexpr int AOFF = (MODE == 0) ? 896 : 0;
    constexpr int NT = K / 64;     // 14 / 28 / 42
    extern __shared__ __align__(16) char smem[];
    const uint32_t sb = smem_u32(smem);

    const int tid = threadIdx.x, wid = tid >> 5, l = tid & 31;
    const int cb = blockIdx.x, rb = blockIdx.y;
    const int row0 = rb * 64, col0 = cb * 128;

    // ---- loader: thread -> A half-row (4 cp16) + B full row (8 cp16) ----
    const int arow = tid >> 1, ac = (tid & 1) * 4;   // A row, chunk base (0 or 4)
    const __half* pA = g_A + (size_t)(row0 + arow) * KMAX + AOFF + ac * 8;
    const __half* pB = W + (size_t)(col0 + tid) * K;
    const uint32_t sA = sb + (uint32_t)(arow * ROWB + ac * 16);
    const uint32_t sB = sb + T_B + (uint32_t)(tid * ROWB);

    int nextk = 0;
    auto issue = [&]() {
        const uint32_t so = (uint32_t)((nextk >> 6) & 1) * STAGE_B;
#pragma unroll
        for (int c = 0; c < 4; c++) cp16(sA + so + c * 16, pA + c * 8);
#pragma unroll
        for (int c = 0; c < 8; c++) cp16(sB + so + c * 16, pB + c * 8);
        CP_COMMIT();
        nextk += 64;
        int adv = 64;
        if (MODE == 2 && nextk == DMODEL) adv += DMODEL;  // skip alpha*u slot
        pA += adv; pB += 64;
    };

    // ---- warp tiling: 1 (M) x 4 (N); warp tile 64x32 ----
    const int wNc = wid * 32;
    const int lq = l >> 2, lr = l & 3;

    float acc[4][4][4];
#pragma unroll
    for (int a = 0; a < 4; a++)
#pragma unroll
        for (int b = 0; b < 4; b++)
#pragma unroll
            for (int c = 0; c < 4; c++) acc[a][b][c] = 0.f;

    const uint32_t kHalf = (uint32_t)((l >> 4) * 16);
    const uint32_t aB = sb + T_A + (uint32_t)((l & 15) * ROWB) + kHalf;
    const uint32_t bB = sb + T_B + (uint32_t)((wNc + (l & 15)) * ROWB) + kHalf;

    issue();
    for (int t = 0; t < NT; t++) {
        CP_WAIT0();
        __syncthreads();
        if (t + 1 < NT) issue();

        const uint32_t stb = (uint32_t)(t & 1) * STAGE_B;
#pragma unroll
        for (int s2 = 0; s2 < 4; s2++) {
            const uint32_t off = stb + (uint32_t)(s2 * 32);
            uint32_t bh[2][4];
#pragma unroll
            for (int nj = 0; nj < 2; nj++)
                ldmx4(bh[nj], bB + off + (uint32_t)(nj * 16 * ROWB));
#pragma unroll
            for (int mi = 0; mi < 4; mi++) {
                uint32_t af[4];
                ldmx4(af, aB + off + (uint32_t)(mi * 16 * ROWB));
#pragma unroll
                for (int nj = 0; nj < 2; nj++) {
                    mma16816(acc[mi][nj * 2 + 0], af, bh[nj][0], bh[nj][2]);
                    mma16816(acc[mi][nj * 2 + 1], af, bh[nj][1], bh[nj][3]);
                }
            }
        }
        // no trailing sync: next iteration's top-of-loop sync orders buffer reuse
    }

    // ---- epilogues (rows: mi*16 + lq + rr*8, 0..63; cols: wNc + n8*8 + lr*2) ----
    if (MODE == 0) {
        __syncthreads();
        float* red = (float*)smem;  // [64][4]
#pragma unroll
        for (int mi = 0; mi < 4; mi++) {
#pragma unroll
            for (int rr = 0; rr < 2; rr++) {
                const int rloc = mi * 16 + lq + rr * 8;
                const float* hrow = hmat + (size_t)(row0 + rloc) * DMODEL + col0 + wNc;
                float s = 0.f;
#pragma unroll
                for (int n8 = 0; n8 < 4; n8++) {
                    const int cc = n8 * 8 + lr * 2;
                    float2 h2 = *(const float2*)(hrow + cc);
                    float2 bb = *(const float2*)(bias + col0 + wNc + cc);
                    s += h2.x * (acc[mi][n8][rr * 2 + 0] + bb.x)
                       + h2.y * (acc[mi][n8][rr * 2 + 1] + bb.y);
                }
                s += __shfl_xor_sync(0xffffffffu, s, 1);
                s += __shfl_xor_sync(0xffffffffu, s, 2);
                if (lr == 0) red[rloc * 4 + wid] = s;
            }
        }
        __syncthreads();
        if (tid < 64) {
            float s = red[tid * 4] + red[tid * 4 + 1] + red[tid * 4 + 2] + red[tid * 4 + 3];
            g_logit_part[(size_t)(row0 + tid) * 8 + cb] = s;
        }
    } else if (MODE == 1) {
#pragma unroll
        for (int mi = 0; mi < 4; mi++) {
#pragma unroll
            for (int rr = 0; rr < 2; rr++) {
                const int rg = row0 + mi * 16 + lq + rr * 8;
                const float al = 1.f / (1.f + __expf(-g_logit[rg] * INV_SQRT_D));
                const float* urow = umat + (size_t)rg * DMODEL + col0 + wNc;
                const float* hrow = hmat + (size_t)rg * DMODEL + col0 + wNc;
                const size_t base1 = (size_t)rg * KMAX + 2 * DMODEL + col0 + wNc;  // ug
                const size_t base2 = (size_t)rg * KMAX + 3 * DMODEL + col0 + wNc;  // h*ug
#pragma unroll
                for (int n8 = 0; n8 < 4; n8++) {
                    const int cc = n8 * 8 + lr * 2;
                    float2 bb = *(const float2*)(bias + col0 + wNc + cc);
                    float2 u2 = *(const float2*)(urow + cc);
                    float2 h2 = *(const float2*)(hrow + cc);
                    float z0 = acc[mi][n8][rr * 2 + 0] + bb.x;
                    float z1 = acc[mi][n8][rr * 2 + 1] + bb.y;
                    float2 o;
                    o.x = al * u2.x / (1.f + __expf(-z0));
                    o.y = al * u2.y / (1.f + __expf(-z1));
                    f16_store2(g_A, base1 + cc, o);
                    f16_store2(g_A, base2 + cc, make_float2(o.x * h2.x, o.y * h2.y));
                }
            }
        }
    } else {
#pragma unroll
        for (int mi = 0; mi < 4; mi++) {
#pragma unroll
            for (int rr = 0; rr < 2; rr++) {
                const int rg = row0 + mi * 16 + lq + rr * 8;
                float* orow = dst + (size_t)rg * DMODEL + col0 + wNc;
#pragma unroll
                for (int n8 = 0; n8 < 4; n8++) {
                    const int cc = n8 * 8 + lr * 2;
                    float2 bb = *(const float2*)(bias + col0 + wNc + cc);
                    float z0 = acc[mi][n8][rr * 2 + 0] + bb.x;
                    float z1 = acc[mi][n8][rr * 2 + 1] + bb.y;
                    float2 o;
                    o.x = 0.5f * z0 * (1.f + erff(z0 * 0.70710678f));
                    o.y = 0.5f * z1 * (1.f + erff(z1 * 0.70710678f));
                    *(float2*)(orow + cc) = o;
                }
            }
        }
    }
}

extern "C" void kernel_launch(void* const* d_in, const int* in_sizes, int n_in,
                              void* d_out, int out_size) {
    const float* h_t   = (const float*)d_in[0];
    const float* u_t   = (const float*)d_in[1];
    const float* W_a_w = (const float*)d_in[4];
    const float* W_a_b = (const float*)d_in[5];
    const float* W_g_w = (const float*)d_in[6];
    const float* W_g_b = (const float*)d_in[7];
    const float* W_f_w = (const float*)d_in[8];
    const float* W_f_b = (const float*)d_in[9];
    float* out = (float*)d_out;

    cudaFuncSetAttribute(hgemm<0>, cudaFuncAttributeMaxDynamicSharedMemorySize, SMEM_BYTES);
    cudaFuncSetAttribute(hgemm<1>, cudaFuncAttributeMaxDynamicSharedMemorySize, SMEM_BYTES);
    cudaFuncSetAttribute(hgemm<2>, cudaFuncAttributeMaxDynamicSharedMemorySize, SMEM_BYTES);

    __half *Wa, *Wg, *Wf;
    cudaGetSymbolAddress((void**)&Wa, g_Wa);
    cudaGetSymbolAddress((void**)&Wg, g_Wg);
    cudaGetSymbolAddress((void**)&Wf, g_Wf);

    dim3 grid(7, N_TOK / 64);   // (7, 256) = 1792 CTAs, 4/SM
    const int nConv = (NA_ITEMS + NW_ITEMS + 255) / 256;

    // 5 launches; #4 (hgemm<1>) is the ncu-captured launch
    k_conv_all<<<nConv, 256>>>(h_t, u_t, W_a_w, W_g_w, W_f_w);            // 1
    hgemm<0><<<grid, 128, SMEM_BYTES>>>(h_t, u_t, Wa, W_a_b, nullptr);    // 2
    k_alpha<<<N_TOK / 8, 256>>>(u_t);                                     // 3
    hgemm<1><<<grid, 128, SMEM_BYTES>>>(h_t, u_t, Wg, W_g_b, nullptr);    // 4
    hgemm<2><<<grid, 128, SMEM_BYTES>>>(h_t, u_t, Wf, W_f_b, out);        // 5
}

// round 17
// speedup vs baseline: 1.5819x; 1.5819x over previous
#include <cuda_runtime.h>
#include <cuda_fp16.h>
#include <math.h>
#include <cstdint>

#define N_TOK 16384
#define DMODEL 896
#define KMAX 3584   // [h | alpha*u | ug | h*ug]
#define INV_SQRT_D 0.03340766f

// ---------------- scratch (device globals) ----------------
__device__ float g_logit_part[N_TOK * 8];
__device__ float g_logit[N_TOK];
__device__ __align__(16) __half g_A[(size_t)N_TOK * KMAX];          // f16 activations
__device__ __align__(16) __half g_Wa[DMODEL * DMODEL];
__device__ __align__(16) __half g_Wg[DMODEL * 2 * DMODEL];
__device__ __align__(16) __half g_Wf[DMODEL * 3 * DMODEL];

// ---------------- helpers ----------------
static __device__ __forceinline__ uint32_t smem_u32(const void* p) {
    uint32_t a;
    asm("{ .reg .u64 t; cvta.to.shared.u64 t, %1; cvt.u32.u64 %0, t; }" : "=r"(a) : "l"(p));
    return a;
}
static __device__ __forceinline__ void cp16(uint32_t s, const void* g) {
    asm volatile("cp.async.cg.shared.global [%0], [%1], 16;" :: "r"(s), "l"(g));
}
#define CP_COMMIT() asm volatile("cp.async.commit_group;" ::: "memory")
#define CP_WAIT0()  asm volatile("cp.async.wait_group 0;" ::: "memory")

static __device__ __forceinline__ void ldmx4(uint32_t* r, uint32_t addr) {
    asm volatile("ldmatrix.sync.aligned.m8n8.x4.shared.b16 {%0,%1,%2,%3}, [%4];"
        : "=r"(r[0]), "=r"(r[1]), "=r"(r[2]), "=r"(r[3]) : "r"(addr));
}
static __device__ __forceinline__ void mma16816(float* c, const uint32_t* a,
                                                uint32_t b0, uint32_t b1) {
    asm volatile("mma.sync.aligned.m16n8k16.row.col.f32.f16.f16.f32 "
        "{%0,%1,%2,%3}, {%4,%5,%6,%7}, {%8,%9}, {%0,%1,%2,%3};"
        : "+f"(c[0]), "+f"(c[1]), "+f"(c[2]), "+f"(c[3])
        : "r"(a[0]), "r"(a[1]), "r"(a[2]), "r"(a[3]), "r"(b0), "r"(b1));
}

static __device__ __forceinline__ void f16_store4(__half* dst, size_t idx, float4 v) {
    uint32_t p01, p23;
    asm("cvt.rn.f16x2.f32 %0, %1, %2;" : "=r"(p01) : "f"(v.y), "f"(v.x));
    asm("cvt.rn.f16x2.f32 %0, %1, %2;" : "=r"(p23) : "f"(v.w), "f"(v.z));
    *(uint2*)(dst + idx) = make_uint2(p01, p23);
}
static __device__ __forceinline__ void f16_store2(__half* dst, size_t idx, float2 v) {
    uint32_t p;
    asm("cvt.rn.f16x2.f32 %0, %1, %2;" : "=r"(p) : "f"(v.y), "f"(v.x));
    *(uint32_t*)(dst + idx) = p;
}

// ---------------- fused conversion kernel (2 float4 groups per thread) ----------------
#define NA_ITEMS (N_TOK * 224 * 2)
#define NW_ITEMS (DMODEL * (DMODEL + 2 * DMODEL + 3 * DMODEL) / 4)
#define CONV_TOT (NA_ITEMS + NW_ITEMS)
static __device__ __forceinline__ void conv_one(
    int i, const float* __restrict__ h, const float* __restrict__ u,
    const float* __restrict__ wa, const float* __restrict__ wg,
    const float* __restrict__ wf) {
    const int half = N_TOK * 224;
    if (i < half) {
        int row = i / 224, c4 = (i % 224) * 4;
        f16_store4(g_A, (size_t)row * KMAX + c4,
                   *(const float4*)(h + (size_t)row * DMODEL + c4));
    } else if (i < 2 * half) {
        int j = i - half;
        int row = j / 224, c4 = (j % 224) * 4;
        f16_store4(g_A, (size_t)row * KMAX + DMODEL + c4,
                   *(const float4*)(u + (size_t)row * DMODEL + c4));
    } else {
        int j = i - 2 * half;
        const int n1 = DMODEL * DMODEL / 4;
        const int n2 = DMODEL * 2 * DMODEL / 4;
        const int n3 = DMODEL * 3 * DMODEL / 4;
        if (j < n1) {
            f16_store4(g_Wa, (size_t)j * 4, ((const float4*)wa)[j]);
        } else if (j < n1 + n2) {
            int k = j - n1;
            f16_store4(g_Wg, (size_t)k * 4, ((const float4*)wg)[k]);
        } else if (j < n1 + n2 + n3) {
            int k = j - n1 - n2;
            f16_store4(g_Wf, (size_t)k * 4, ((const float4*)wf)[k]);
        }
    }
}
__global__ void k_conv_all(const float* __restrict__ h, const float* __restrict__ u,
                           const float* __restrict__ wa, const float* __restrict__ wg,
                           const float* __restrict__ wf) {
    int i = blockIdx.x * (blockDim.x * 2) + threadIdx.x;
    if (i < CONV_TOT) conv_one(i, h, u, wa, wg, wf);
    i += blockDim.x;
    if (i < CONV_TOT) conv_one(i, h, u, wa, wg, wf);
}

// one warp per row: reduce logit partials, compute alpha, write f16 alpha*u into A[896:1792]
__global__ void k_alpha(const float* __restrict__ u) {
    const int row = blockIdx.x * 8 + (threadIdx.x >> 5);
    const int l = threadIdx.x & 31;
    float s = (l < 7) ? g_logit_part[(size_t)row * 8 + l] : 0.f;
    s += __shfl_xor_sync(0xffffffffu, s, 1);
    s += __shfl_xor_sync(0xffffffffu, s, 2);
    s += __shfl_xor_sync(0xffffffffu, s, 4);
    s = __shfl_sync(0xffffffffu, s, 0);
    if (l == 0) g_logit[row] = s;
    const float a = 1.f / (1.f + __expf(-s * INV_SQRT_D));
    const float* ur = u + (size_t)row * DMODEL;
    const size_t base = (size_t)row * KMAX + DMODEL;
#pragma unroll
    for (int j = 0; j < 7; j++) {
        const int c4 = (j * 32 + l) * 4;
        float4 v = *(const float4*)(ur + c4);
        v.x *= a; v.y *= a; v.z *= a; v.w *= a;
        f16_store4(g_A, base + c4, v);
    }
}

// ---------------- f16 single-pass HMMA GEMM: 64x128 CTA tile, 128 thr, 4 CTAs/SM ----------------
#define ROWB    80
#define T_A     0
#define T_B     (64 * ROWB)           // A: 64 rows
#define STAGE_B ((64 + 128) * ROWB)   // 15360
#define SMEM_BYTES (2 * STAGE_B)      // 30720; 4 CTAs = 122880 <= 228KB

// MODE 0: K=896 (A = u slot). Epi: logit partials
// MODE 1: K=1792 (A=[h|alpha u]). Epi: ug -> A[1792:2688], h*ug -> A[2688:3584]
// MODE 2: K=2688 (A = {[0:896),[1792:3584)}). Epi: dst = gelu_erf(z)
template <int MODE>
__global__ void __launch_bounds__(128, 4) hgemm(
    const float* __restrict__ hmat, const float* __restrict__ umat,
    const __half* __restrict__ W, const float* __restrict__ bias,
    float* __restrict__ dst)
{
    constexpr int K = (MODE == 0) ? 896 : (MODE == 1 ? 1792 : 2688);
    constexpr int AOFF = (MODE == 0) ? 896 : 0;
    constexpr int NT = K / 32;
    extern __shared__ __align__(16) char smem[];
    const uint32_t sb = smem_u32(smem);

    const int tid = threadIdx.x, wid = tid >> 5, l = tid & 31;
    const int cb = blockIdx.x, rb = blockIdx.y;
    const int row0 = rb * 64, col0 = cb * 128;

    // ---- loader: thread -> 6 fixed rows (2 A + 4 B), fixed 16B chunk ----
    const int r0 = tid >> 2, sub = tid & 3;       // r0: 0..31, sub: 0..3
    const __half* pA0 = g_A + (size_t)(row0 + r0) * KMAX + AOFF + sub * 8;
    const __half* pA1 = g_A + (size_t)(row0 + r0 + 32) * KMAX + AOFF + sub * 8;
    const __half* pB0 = W + (size_t)(col0 + r0) * K + sub * 8;
    const __half* pB1 = W + (size_t)(col0 + r0 + 32) * K + sub * 8;
    const __half* pB2 = W + (size_t)(col0 + r0 + 64) * K + sub * 8;
    const __half* pB3 = W + (size_t)(col0 + r0 + 96) * K + sub * 8;
    const uint32_t sA0 = sb + (uint32_t)(r0 * ROWB + sub * 16);
    const uint32_t sA1 = sA0 + 32 * ROWB;
    const uint32_t sB0 = sb + T_B + (uint32_t)(r0 * ROWB + sub * 16);

    int nextk = 0;
    auto issue = [&]() {
        const uint32_t so = (uint32_t)((nextk >> 5) & 1) * STAGE_B;
        cp16(sA0 + so, pA0);
        cp16(sA1 + so, pA1);
        cp16(sB0 + so, pB0);
        cp16(sB0 + so + 32 * ROWB, pB1);
        cp16(sB0 + so + 64 * ROWB, pB2);
        cp16(sB0 + so + 96 * ROWB, pB3);
        CP_COMMIT();
        nextk += 32;
        int adv = 32;
        if (MODE == 2 && nextk == DMODEL) adv += DMODEL;  // skip alpha*u slot
        pA0 += adv; pA1 += adv; pB0 += 32; pB1 += 32; pB2 += 32; pB3 += 32;
    };

    // ---- warp tiling: 1 (M) x 4 (N); warp tile 64x32 ----
    const int wNc = wid * 32;
    const int lq = l >> 2, lr = l & 3;

    float acc[4][4][4];
#pragma unroll
    for (int a = 0; a < 4; a++)
#pragma unroll
        for (int b = 0; b < 4; b++)
#pragma unroll
            for (int c = 0; c < 4; c++) acc[a][b][c] = 0.f;

    const uint32_t kHalf = (uint32_t)((l >> 4) * 16);
    const uint32_t aB = sb + T_A + (uint32_t)((l & 15) * ROWB) + kHalf;
    const uint32_t bB = sb + T_B + (uint32_t)((wNc + (l & 15)) * ROWB) + kHalf;

    issue();
    for (int t = 0; t < NT; t++) {
        CP_WAIT0();
        __syncthreads();
        if (t + 1 < NT) issue();

        const uint32_t stb = (uint32_t)(t & 1) * STAGE_B;
#pragma unroll
        for (int s2 = 0; s2 < 2; s2++) {
            const uint32_t off = stb + (uint32_t)(s2 * 32);
            uint32_t bh[2][4];
#pragma unroll
            for (int nj = 0; nj < 2; nj++)
                ldmx4(bh[nj], bB + off + (uint32_t)(nj * 16 * ROWB));
#pragma unroll
            for (int mi = 0; mi < 4; mi++) {
                uint32_t af[4];
                ldmx4(af, aB + off + (uint32_t)(mi * 16 * ROWB));
#pragma unroll
                for (int nj = 0; nj < 2; nj++) {
                    mma16816(acc[mi][nj * 2 + 0], af, bh[nj][0], bh[nj][2]);
                    mma16816(acc[mi][nj * 2 + 1], af, bh[nj][1], bh[nj][3]);
                }
            }
        }
        __syncthreads();
    }

    // ---- epilogues (rows: mi*16 + lq + rr*8, 0..63; cols: wNc + n8*8 + lr*2) ----
    if (MODE == 0) {
        __syncthreads();
        float* red = (float*)smem;  // [64][4]
#pragma unroll
        for (int mi = 0; mi < 4; mi++) {
#pragma unroll
            for (int rr = 0; rr < 2; rr++) {
                const int rloc = mi * 16 + lq + rr * 8;
                const float* hrow = hmat + (size_t)(row0 + rloc) * DMODEL + col0 + wNc;
                float s = 0.f;
#pragma unroll
                for (int n8 = 0; n8 < 4; n8++) {
                    const int cc = n8 * 8 + lr * 2;
                    float2 h2 = *(const float2*)(hrow + cc);
                    float2 bb = *(const float2*)(bias + col0 + wNc + cc);
                    s += h2.x * (acc[mi][n8][rr * 2 + 0] + bb.x)
                       + h2.y * (acc[mi][n8][rr * 2 + 1] + bb.y);
                }
                s += __shfl_xor_sync(0xffffffffu, s, 1);
                s += __shfl_xor_sync(0xffffffffu, s, 2);
                if (lr == 0) red[rloc * 4 + wid] = s;
            }
        }
        __syncthreads();
        if (tid < 64) {
            float s = red[tid * 4] + red[tid * 4 + 1] + red[tid * 4 + 2] + red[tid * 4 + 3];
            g_logit_part[(size_t)(row0 + tid) * 8 + cb] = s;
        }
    } else if (MODE == 1) {
#pragma unroll
        for (int mi = 0; mi < 4; mi++) {
#pragma unroll
            for (int rr = 0; rr < 2; rr++) {
                const int rg = row0 + mi * 16 + lq + rr * 8;
                const float al = 1.f / (1.f + __expf(-g_logit[rg] * INV_SQRT_D));
                const float* urow = umat + (size_t)rg * DMODEL + col0 + wNc;
                const float* hrow = hmat + (size_t)rg * DMODEL + col0 + wNc;
                const size_t base1 = (size_t)rg * KMAX + 2 * DMODEL + col0 + wNc;  // ug
                const size_t base2 = (size_t)rg * KMAX + 3 * DMODEL + col0 + wNc;  // h*ug
#pragma unroll
                for (int n8 = 0; n8 < 4; n8++) {
                    const int cc = n8 * 8 + lr * 2;
                    float2 bb = *(const float2*)(bias + col0 + wNc + cc);
                    float2 u2 = *(const float2*)(urow + cc);
                    float2 h2 = *(const float2*)(hrow + cc);
                    float z0 = acc[mi][n8][rr * 2 + 0] + bb.x;
                    float z1 = acc[mi][n8][rr * 2 + 1] + bb.y;
                    float2 o;
                    o.x = al * u2.x / (1.f + __expf(-z0));
                    o.y = al * u2.y / (1.f + __expf(-z1));
                    f16_store2(g_A, base1 + cc, o);
                    f16_store2(g_A, base2 + cc, make_float2(o.x * h2.x, o.y * h2.y));
                }
            }
        }
    } else {
#pragma unroll
        for (int mi = 0; mi < 4; mi++) {
#pragma unroll
            for (int rr = 0; rr < 2; rr++) {
                const int rg = row0 + mi * 16 + lq + rr * 8;
                float* orow = dst + (size_t)rg * DMODEL + col0 + wNc;
#pragma unroll
                for (int n8 = 0; n8 < 4; n8++) {
                    const int cc = n8 * 8 + lr * 2;
                    float2 bb = *(const float2*)(bias + col0 + wNc + cc);
                    float z0 = acc[mi][n8][rr * 2 + 0] + bb.x;
                    float z1 = acc[mi][n8][rr * 2 + 1] + bb.y;
                    float2 o;
                    o.x = 0.5f * z0 * (1.f + erff(z0 * 0.70710678f));
                    o.y = 0.5f * z1 * (1.f + erff(z1 * 0.70710678f));
                    *(float2*)(orow + cc) = o;
                }
            }
        }
    }
}

extern "C" void kernel_launch(void* const* d_in, const int* in_sizes, int n_in,
                              void* d_out, int out_size) {
    const float* h_t   = (const float*)d_in[0];
    const float* u_t   = (const float*)d_in[1];
    const float* W_a_w = (const float*)d_in[4];
    const float* W_a_b = (const float*)d_in[5];
    const float* W_g_w = (const float*)d_in[6];
    const float* W_g_b = (const float*)d_in[7];
    const float* W_f_w = (const float*)d_in[8];
    const float* W_f_b = (const float*)d_in[9];
    float* out = (float*)d_out;

    cudaFuncSetAttribute(hgemm<0>, cudaFuncAttributeMaxDynamicSharedMemorySize, SMEM_BYTES);
    cudaFuncSetAttribute(hgemm<1>, cudaFuncAttributeMaxDynamicSharedMemorySize, SMEM_BYTES);
    cudaFuncSetAttribute(hgemm<2>, cudaFuncAttributeMaxDynamicSharedMemorySize, SMEM_BYTES);

    __half *Wa, *Wg, *Wf;
    cudaGetSymbolAddress((void**)&Wa, g_Wa);
    cudaGetSymbolAddress((void**)&Wg, g_Wg);
    cudaGetSymbolAddress((void**)&Wf, g_Wf);

    dim3 grid(7, N_TOK / 64);   // (7, 256) = 1792 CTAs, 4/SM
    const int nConv = (CONV_TOT + 511) / 512;

    // 5 launches; #4 (hgemm<1>) is the ncu-captured launch
    k_conv_all<<<nConv, 256>>>(h_t, u_t, W_a_w, W_g_w, W_f_w);            // 1
    hgemm<0><<<grid, 128, SMEM_BYTES>>>(h_t, u_t, Wa, W_a_b, nullptr);    // 2
    k_alpha<<<N_TOK / 8, 256>>>(u_t);                                     // 3
    hgemm<1><<<grid, 128, SMEM_BYTES>>>(h_t, u_t, Wg, W_g_b, nullptr);    // 4
    hgemm<2><<<grid, 128, SMEM_BYTES>>>(h_t, u_t, Wf, W_f_b, out);        // 5
}